// round 2
// baseline (speedup 1.0000x reference)
#include <cuda_runtime.h>
#include <cstdint>
#include <cstddef>

// Problem constants (fixed shapes for this problem)
#define BATCH   8192
#define IN_DIM  4096
#define HID     16384
#define KSEL    64

// -------- scratch (allocation-free: __device__ globals) --------
__device__ float g_features[(size_t)BATCH * HID];    // 512 MB
__device__ float g_wdecT[(size_t)HID * IN_DIM];      // 256 MB, W_dec transposed [HID, IN_DIM]
__device__ float g_vals[BATCH * KSEL];
__device__ int   g_idx [BATCH * KSEL];

// ============================================================================
// Kernel 1: transpose W_dec [IN_DIM, HID] -> g_wdecT [HID, IN_DIM]
// ============================================================================
__global__ void wdec_transpose(const float* __restrict__ W)
{
    __shared__ float tile[32][33];
    int h0 = blockIdx.x * 32;
    int d0 = blockIdx.y * 32;
    int tx = threadIdx.x, ty = threadIdx.y;   // block (32, 8)
#pragma unroll
    for (int r = 0; r < 32; r += 8)
        tile[ty + r][tx] = W[(size_t)(d0 + ty + r) * HID + (h0 + tx)];
    __syncthreads();
#pragma unroll
    for (int r = 0; r < 32; r += 8)
        g_wdecT[(size_t)(h0 + ty + r) * IN_DIM + (d0 + tx)] = tile[tx][ty + r];
}

// ============================================================================
// Kernel 2: encoder SGEMM with COMPENSATED accumulation
//   features = relu(x @ W_enc^T + b_enc)
//   Per 8-term k-chunk: plain FFMA chain (error ~2.5e-9), folded into a
//   TwoSum float-float spine (exact). Net dot-product error ~6e-8 absolute,
//   i.e. features are near-correctly-rounded fp32. This removes top-k
//   boundary swaps caused by serial-accumulation rounding drift.
// ============================================================================
__global__ __launch_bounds__(256, 1) void encoder_gemm(
    const float* __restrict__ x,
    const float* __restrict__ W,
    const float* __restrict__ bias)
{
    const int BM = 128, BN = 128, BK = 8;
    __shared__ float As[BK][BM + 4];
    __shared__ float Bs[BK][BN + 4];

    int tid = threadIdx.x;
    int tx  = tid % 16;          // 0..15 -> 8 cols each
    int ty  = tid / 16;          // 0..15 -> 8 rows each
    int m0  = blockIdx.y * BM;
    int n0  = blockIdx.x * BN;

    // global load mapping: 128 rows x 8 k-floats = 1024 floats = 256 x float4
    int lr = tid >> 1;           // 0..127: row within tile
    int lc = (tid & 1) * 4;      // 0 or 4: k offset

    const float* Ap = x + (size_t)(m0 + lr) * IN_DIM + lc;
    const float* Bp = W + (size_t)(n0 + lr) * IN_DIM + lc;

    float s[8][8];   // leading sums
    float c[8][8];   // compensation
#pragma unroll
    for (int i = 0; i < 8; i++)
#pragma unroll
        for (int j = 0; j < 8; j++) { s[i][j] = 0.0f; c[i][j] = 0.0f; }

    for (int k0 = 0; k0 < IN_DIM; k0 += BK) {
        float4 a4 = *(const float4*)(Ap + k0);
        float4 b4 = *(const float4*)(Bp + k0);
        __syncthreads();
        As[lc + 0][lr] = a4.x; As[lc + 1][lr] = a4.y;
        As[lc + 2][lr] = a4.z; As[lc + 3][lr] = a4.w;
        Bs[lc + 0][lr] = b4.x; Bs[lc + 1][lr] = b4.y;
        Bs[lc + 2][lr] = b4.z; Bs[lc + 3][lr] = b4.w;
        __syncthreads();

        // 8-term chunk accumulators (fresh each k0)
        float r[8][8];
#pragma unroll
        for (int kk = 0; kk < BK; kk++) {
            float ra[8], rb[8];
            *(float4*)(&ra[0]) = *(const float4*)(&As[kk][ty * 8 + 0]);
            *(float4*)(&ra[4]) = *(const float4*)(&As[kk][ty * 8 + 4]);
            *(float4*)(&rb[0]) = *(const float4*)(&Bs[kk][tx * 8 + 0]);
            *(float4*)(&rb[4]) = *(const float4*)(&Bs[kk][tx * 8 + 4]);
            if (kk == 0) {
#pragma unroll
                for (int i = 0; i < 8; i++)
#pragma unroll
                    for (int j = 0; j < 8; j++)
                        r[i][j] = ra[i] * rb[j];
            } else {
#pragma unroll
                for (int i = 0; i < 8; i++)
#pragma unroll
                    for (int j = 0; j < 8; j++)
                        r[i][j] = fmaf(ra[i], rb[j], r[i][j]);
            }
        }

        // fold chunk into compensated spine: (s, c) += r via full TwoSum
#pragma unroll
        for (int i = 0; i < 8; i++)
#pragma unroll
            for (int j = 0; j < 8; j++) {
                float rr = r[i][j];
                float t  = s[i][j] + rr;
                float z  = t - s[i][j];
                float e  = (s[i][j] - (t - z)) + (rr - z);
                c[i][j] += e;
                s[i][j]  = t;
            }
    }

    // epilogue: collapse, bias + relu, write to g_features
    int crow = m0 + ty * 8;
    int ccol = n0 + tx * 8;
    float bv[8];
    *(float4*)(&bv[0]) = *(const float4*)(&bias[ccol + 0]);
    *(float4*)(&bv[4]) = *(const float4*)(&bias[ccol + 4]);
#pragma unroll
    for (int i = 0; i < 8; i++) {
        float* orow = g_features + (size_t)(crow + i) * HID + ccol;
        float o[8];
#pragma unroll
        for (int j = 0; j < 8; j++) {
            float dot = s[i][j] + c[i][j];   // near-correctly-rounded dot
            o[j] = fmaxf(dot + bv[j], 0.0f);
        }
        *(float4*)(orow + 0) = *(float4*)(&o[0]);
        *(float4*)(orow + 4) = *(float4*)(&o[4]);
    }
}

// ============================================================================
// Kernel 3: per-row top-k (k=64) via 4x8-bit radix select on float bits
// (all features >= 0 after relu -> uint bits order-preserving; -0.0 guarded).
// Writes the sparse row to out_sf and compacts (val, idx) deterministically
// (index order) for the decoder.
// Dynamic shared: sbits[16384] + hist[256] + keep[512] words
// ============================================================================
#define TOPK_SMEM_WORDS (HID + 256 + (HID / 32))
__global__ __launch_bounds__(256) void topk_kernel(float* __restrict__ out_sf)
{
    extern __shared__ uint32_t sh[];
    uint32_t* sbits = sh;                 // HID
    uint32_t* hist  = sh + HID;           // 256
    uint32_t* keep  = sh + HID + 256;     // HID/32 = 512
    __shared__ uint32_t s_prefix, s_krem, s_cnteq;

    int row = blockIdx.x;
    int tid = threadIdx.x;
    const float* frow = g_features + (size_t)row * HID;

    for (int i = tid; i < HID; i += 256) {
        uint32_t v = __float_as_uint(frow[i]);
        if (v == 0x80000000u) v = 0u;     // -0.0 -> +0.0
        sbits[i] = v;
    }
    if (tid == 0) { s_prefix = 0u; s_krem = KSEL; }
    __syncthreads();

    // 4 radix passes, MSB first
    for (int shift = 24; shift >= 0; shift -= 8) {
        hist[tid & 255] = 0;              // 256 threads -> zero 256 bins
        __syncthreads();
        uint32_t pmask = (shift == 24) ? 0u : (0xFFFFFFFFu << (shift + 8));
        uint32_t pref  = s_prefix;
        for (int i = tid; i < HID; i += 256) {
            uint32_t v = sbits[i];
            if ((v & pmask) == pref)
                atomicAdd(&hist[(v >> shift) & 0xFFu], 1u);
        }
        __syncthreads();
        if (tid == 0) {
            uint32_t krem = s_krem, cum = 0;
            int d = 255;
            for (; d > 0; d--) {
                if (cum + hist[d] >= krem) break;
                cum += hist[d];
            }
            s_prefix = pref | ((uint32_t)d << shift);
            s_krem   = krem - cum;
            s_cnteq  = hist[d];
        }
        __syncthreads();
    }

    uint32_t T     = s_prefix;
    uint32_t need  = s_krem;    // how many elements == T to keep
    uint32_t cnteq = s_cnteq;   // how many elements == T exist

    // build keep bitmap (deterministic)
    if (cnteq == need) {
        // common case: keep everything >= T
        for (int w = tid; w < HID / 32; w += 256) {
            uint32_t m = 0;
#pragma unroll
            for (int b = 0; b < 32; b++)
                if (sbits[w * 32 + b] >= T) m |= (1u << b);
            keep[w] = m;
        }
    } else {
        // rare tie case: lowest-index ties win (matches lax.top_k stability)
        if (tid == 0) {
            uint32_t eqc = 0;
            for (int w = 0; w < HID / 32; w++) {
                uint32_t m = 0;
                for (int b = 0; b < 32; b++) {
                    uint32_t v = sbits[w * 32 + b];
                    bool kp = false;
                    if (v > T) kp = true;
                    else if (v == T) { if (eqc < need) kp = true; eqc++; }
                    if (kp) m |= (1u << b);
                }
                keep[w] = m;
            }
        }
    }
    __syncthreads();

    // sparse output row (coalesced)
    float* orow = out_sf + (size_t)row * HID;
    for (int i = tid; i < HID; i += 256) {
        bool kp = (keep[i >> 5] >> (i & 31)) & 1u;
        orow[i] = kp ? __uint_as_float(sbits[i]) : 0.0f;
    }

    // deterministic compaction (warp 0, index order)
    if (tid < 32) {
        int cnt = 0;
        for (int base = 0; base < HID; base += 32) {
            uint32_t m = keep[base >> 5];
            bool kp = (m >> tid) & 1u;
            int r = __popc(m & ((1u << tid) - 1u));
            if (kp) {
                g_vals[row * KSEL + cnt + r] = __uint_as_float(sbits[base + tid]);
                g_idx [row * KSEL + cnt + r] = base + tid;
            }
            cnt += __popc(m);
        }
    }
}

// ============================================================================
// Kernel 4: sparse decode  recon[b,:] = sum_j v_j * W_dec^T[h_j, :]
// One block per row; 256 threads x 4 float4 = 4096 cols.
// ============================================================================
__global__ __launch_bounds__(256) void decoder_kernel(float* __restrict__ out_rec)
{
    int row = blockIdx.x;
    int tid = threadIdx.x;
    __shared__ float sv[KSEL];
    __shared__ int   si[KSEL];
    if (tid < KSEL) { sv[tid] = g_vals[row * KSEL + tid]; si[tid] = g_idx[row * KSEL + tid]; }
    __syncthreads();

    float4 acc[4];
#pragma unroll
    for (int w = 0; w < 4; w++) acc[w] = make_float4(0.f, 0.f, 0.f, 0.f);

    for (int j = 0; j < KSEL; j++) {
        float v = sv[j];
        const float4* wp = (const float4*)(g_wdecT + (size_t)si[j] * IN_DIM);
#pragma unroll
        for (int w = 0; w < 4; w++) {
            float4 t = wp[tid + w * 256];
            acc[w].x = fmaf(v, t.x, acc[w].x);
            acc[w].y = fmaf(v, t.y, acc[w].y);
            acc[w].z = fmaf(v, t.z, acc[w].z);
            acc[w].w = fmaf(v, t.w, acc[w].w);
        }
    }
    float4* op = (float4*)(out_rec + (size_t)row * IN_DIM);
#pragma unroll
    for (int w = 0; w < 4; w++) op[tid + w * 256] = acc[w];
}

// ============================================================================
// launch
// ============================================================================
extern "C" void kernel_launch(void* const* d_in, const int* in_sizes, int n_in,
                              void* d_out, int out_size)
{
    const float* x     = (const float*)d_in[0];   // [8192, 4096]
    const float* W_enc = (const float*)d_in[1];   // [16384, 4096]
    const float* b_enc = (const float*)d_in[2];   // [16384]
    const float* W_dec = (const float*)d_in[3];   // [4096, 16384]
    // d_in[4] = k (always 64 for this problem)

    float* out_sf  = (float*)d_out;                          // [8192, 16384]
    float* out_rec = out_sf + (size_t)BATCH * HID;           // [8192, 4096]

    // 1) transpose W_dec for coalesced sparse decode
    wdec_transpose<<<dim3(HID / 32, IN_DIM / 32), dim3(32, 8)>>>(W_dec);

    // 2) encoder GEMM (compensated) + bias + relu
    encoder_gemm<<<dim3(HID / 128, BATCH / 128), 256>>>(x, W_enc, b_enc);

    // 3) top-k select + sparse scatter + compaction
    size_t topk_smem = (size_t)TOPK_SMEM_WORDS * sizeof(uint32_t);
    cudaFuncSetAttribute(topk_kernel, cudaFuncAttributeMaxDynamicSharedMemorySize,
                         (int)topk_smem);
    topk_kernel<<<BATCH, 256, topk_smem>>>(out_sf);

    // 4) sparse decode
    decoder_kernel<<<BATCH, 256>>>(out_rec);
}